// round 17
// baseline (speedup 1.0000x reference)
#include <cuda_runtime.h>
#include <math.h>

#define NP    4096
#define NC    45       // cells per side
#define NCELL 2025
#define CPAD  2048
#define CAPT  12       // per-particle collision candidate cap
#define NBLK  4
#define NTHR  1024
#define PPT   4        // NP / NTHR

#define PI_F     3.1415927410125732f
#define TWOPI_F  6.2831854820251465f

// global scratch (no allocation allowed)
static __device__ float2         g_pos[NP];        // translated positions
static __device__ unsigned short g_nbr[CAPT * NP]; // [k][i] collision candidates
static __device__ unsigned char  g_cnt[NP];
static __device__ int            g_done;           // zero-init; reset by sweep block

#define INV_CELL ((float)NC / 1.28e-3f)

// smem layouts (dynamic, bytes):
//  pair view : s_p f2 0..32K | s_o f2 32K..64K | s_hc 64K..72K | s_scan 72K..80K |
//              s_cell 80K..88K | s_srt 88K..96K
//  sweep view: s_pos f2 0..32K | s_nbr2 u16 32K..128K | s_lbl u16 128K..136K |
//              s_ca u8 136K..140K | s_sc2 u32 140K..156K | s_comp u16 156K..164K |
//              s_mv f2 (alias cursors u32) 164K..196K
#define SMEM_BYTES 200704

__global__ void __launch_bounds__(NTHR, 1)
fused_kernel(const float* __restrict__ pre, const float* __restrict__ pim,
             const float* __restrict__ ore, const float* __restrict__ oim,
             const float* __restrict__ deltas, const float* __restrict__ rnoise,
             const float* __restrict__ tnre, const float* __restrict__ tnim,
             float* __restrict__ out) {
    extern __shared__ char smem[];
    // pair view
    float2*         s_p    = (float2*)smem;
    float2*         s_o    = (float2*)(smem + 32768);
    unsigned int*   s_hc   = (unsigned int*)(smem + 65536);
    unsigned int*   s_scan = (unsigned int*)(smem + 73728);
    unsigned short* s_cell = (unsigned short*)(smem + 81920);
    unsigned short* s_srt  = (unsigned short*)(smem + 90112);

    __shared__ float s_ws[64];
    __shared__ float s_cms[2];
    __shared__ int   s_last;
    __shared__ int   s_nbig;
    __shared__ unsigned short s_bigl[256];

    int tid = threadIdx.x;
    int lane = tid & 31, wrp = tid >> 5;    // 32 warps

    // ---- pair phase A: load + histogram + cms ----
    s_hc[tid] = 0u; s_hc[tid + NTHR] = 0u;
    __syncthreads();

    float ax = 0.f, ay = 0.f;
    #pragma unroll
    for (int s = 0; s < PPT; s++) {
        int k = tid + s * NTHR;
        float px = pre[k], py = pim[k];
        s_p[k] = make_float2(px, py);
        s_o[k] = make_float2(ore[k], oim[k]);
        int cx = (int)(px * INV_CELL); cx = cx < 0 ? 0 : (cx > NC - 1 ? NC - 1 : cx);
        int cy = (int)(py * INV_CELL); cy = cy < 0 ? 0 : (cy > NC - 1 ? NC - 1 : cy);
        int cell = cy * NC + cx;
        s_cell[k] = (unsigned short)cell;
        atomicAdd(&s_hc[cell], 1u);
        ax += px; ay += py;
    }
    #pragma unroll
    for (int o = 16; o > 0; o >>= 1) {
        ax += __shfl_down_sync(0xffffffffu, ax, o);
        ay += __shfl_down_sync(0xffffffffu, ay, o);
    }
    if (lane == 0) { s_ws[wrp] = ax; s_ws[32 + wrp] = ay; }
    __syncthreads();
    if (tid == 0) {
        float sx = 0.f, sy = 0.f;
        #pragma unroll
        for (int w = 0; w < 32; w++) { sx += s_ws[w]; sy += s_ws[32 + w]; }
        s_cms[0] = sx * (1.0f / NP);        // n_a = 4096 exactly
        s_cms[1] = sy * (1.0f / NP);
    }
    __syncthreads();

    // ---- inclusive scan over 2048 cells: 2 cells/thread + warp shfl ----
    {
        unsigned v0, v1;
        int base = tid * 2;
        v0 = s_hc[base];
        v1 = v0 + s_hc[base + 1];
        unsigned tot = v1;
        #pragma unroll
        for (int o = 1; o < 32; o <<= 1) {
            unsigned n = __shfl_up_sync(0xffffffffu, tot, o);
            if (lane >= o) tot += n;
        }
        if (lane == 31) ((unsigned*)s_ws)[wrp] = tot;
        unsigned lanepre = tot - v1;
        __syncthreads();
        unsigned wpre = 0u;
        #pragma unroll
        for (int w = 0; w < 32; w++) { unsigned t = ((unsigned*)s_ws)[w]; if (w < wrp) wpre += t; }
        unsigned off = wpre + lanepre;
        s_scan[base] = v0 + off;
        s_scan[base + 1] = v1 + off;
    }
    __syncthreads();
    {
        int c0 = tid, c1 = tid + NTHR;
        s_hc[c0] = s_scan[c0] - s_hc[c0];   // cursor = exclusive start
        s_hc[c1] = s_scan[c1] - s_hc[c1];
    }
    __syncthreads();
    #pragma unroll
    for (int s = 0; s < PPT; s++) {
        int k = tid + s * NTHR;
        unsigned pos = atomicAdd(&s_hc[s_cell[k]], 1u);
        s_srt[pos] = (unsigned short)k;
    }
    __syncthreads();

    // ---- pair phase B: neighborhood scan for this block's 1024 particles ----
    const float ROCf  = (float)(2.5e-5 + 3.15e-6);   // RO + RC = 28.15um
    const float ROC2G = ROCf * ROCf * 1.0005f;
    const float RRf   = (float)(8e-6);
    const float RCAP  = (float)(4.5 * 3.15e-6);
    const float RCAP2 = RCAP * RCAP;

    int i = blockIdx.x * NTHR + tid;
    float pxi = s_p[i].x, pyi = s_p[i].y;
    float orr = s_o[i].x, ori = s_o[i].y;

    int cell = s_cell[i];
    int cx = cell % NC, cy = cell / NC;
    int x0 = cx > 0 ? cx - 1 : 0, x1 = cx < NC - 1 ? cx + 1 : NC - 1;
    int y0 = cy > 0 ? cy - 1 : 0, y1 = cy < NC - 1 ? cy + 1 : NC - 1;

    float nr = 0.f, sxv = 0.f, syv = 0.f, oxv = 0.f, oyv = 0.f;
    int cc = 0;

    for (int gy = y0; gy <= y1; gy++) {
        int c0 = gy * NC + x0;
        int c1 = gy * NC + x1;
        int b = (c0 == 0) ? 0 : (int)s_scan[c0 - 1];
        int e = (int)s_scan[c1];
        for (int k = b; k < e; k++) {
            int j = s_srt[k];
            float2 pj = s_p[j];
            float dx = pxi - pj.x, dy = pyi - pj.y;
            float r2 = fmaf(dx, dx, dy * dy);
            bool same = (j == i);
            if (r2 <= ROC2G || same) {
                if (r2 <= RCAP2 && !same) {                 // collision candidate
                    if (cc < CAPT) g_nbr[cc * NP + i] = (unsigned short)j;
                    cc++;
                }
                float dist = same ? 1.0f : __fsqrt_rn(r2);  // diag dist = 1 (eye)
                float2 oj = s_o[j];
                if (dist <= ROCf || same) {                 // mask_ro (self incl.)
                    oxv += oj.x;
                    oyv += oj.y;
                }
                if (dist <= RRf && !same) {                 // mask_rr (self excl.)
                    // in_front: |wrap(ang_i - ang_j)| < pi/2 <=> ori_i . ori_j > 0
                    if (fmaf(orr, oj.x, ori * oj.y) > 0.f) {
                        nr += 1.0f; sxv += pj.x; syv += pj.y;
                    }
                }
            }
        }
    }
    g_cnt[i] = (unsigned char)(cc > CAPT ? CAPT : cc);

    // ---- epilogue ----
    float sgn = (nr > 0.f) ? 1.f : 0.f;
    float den = fmaxf(nr, 1.f);
    float SSx = sxv / den - pxi * sgn;
    float SSy = syv / den - pyi * sgn;
    float ddx = -SSx, ddy = -SSy;

    float Px = s_cms[0] - pxi;               // Ps = cms - pos (Ra = inf)
    float Py = s_cms[1] - pyi;

    float del = deltas[i];
    float cd = cosf(del), sd = sinf(del);
    float lx = Px * cd - Py * sd;
    float ly = Px * sd + Py * cd;
    float rxx = Px * cd + Py * sd;
    float ryy = Py * cd - Px * sd;

    float dl = lx * oxv + ly * oyv;
    float dr = rxx * oxv + ryy * oyv;
    float no = fmaxf(__fsqrt_rn(oxv * oxv + oyv * oyv), 1e-14f);
    float cl = dl / (fmaxf(__fsqrt_rn(lx * lx + ly * ly), 1e-14f) * no);
    float cr = dr / (fmaxf(__fsqrt_rn(rxx * rxx + ryy * ryy), 1e-14f) * no);
    bool usel = (cl >= cr);
    float bx = usel ? lx : rxx;
    float by = usel ? ly : ryy;

    bool hasrep = (ddx != 0.f) || (ddy != 0.f);
    float tx = hasrep ? ddx : bx;
    float ty = hasrep ? ddy : by;
    float att = atan2f(ty, tx) - atan2f(ori, orr);
    if (att <= -PI_F) { float r = fmodf(att, PI_F); if (r < 0.f) r += PI_F; att = r; }
    if (att >= PI_F) att -= TWOPI_F;

    const float CTH  = (float)(0.2 * 25.0 * 0.0028);
    const float S2DR = (float)0.07483314773547883;
    const float SDT  = (float)0.4472135954999579;
    float theta = CTH * sinf(att) + rnoise[i] * S2DR * SDT;
    float rc = cosf(theta), rs = sinf(theta);
    float nore = orr * rc - ori * rs;
    float noim = orr * rs + ori * rc;

    const float CH    = (float)0.7071067811865476;
    const float CTT   = (float)1.6733200530681511e-7;
    const float DTVEL = (float)(0.2 * 5e-7);
    float tnr = tnre[i] * CH * CTT;
    float tni = tnim[i] * CH * CTT;
    g_pos[i] = make_float2(pxi + (DTVEL * orr + tnr * SDT),
                           pyi + (DTVEL * ori + tni * SDT));

    out[(1 * NP + i) * 2 + 0] = nore;
    out[(1 * NP + i) * 2 + 1] = noim;
    out[(2 * NP + i) * 2 + 0] = oxv;
    out[(2 * NP + i) * 2 + 1] = oyv;
    out[(3 * NP + i) * 2 + 0] = lx;
    out[(3 * NP + i) * 2 + 1] = ly;
    out[(4 * NP + i) * 2 + 0] = rxx;
    out[(4 * NP + i) * 2 + 1] = ryy;

    // ---- last-block ticket ----
    __syncthreads();
    if (tid == 0) {
        __threadfence();
        int v = atomicAdd(&g_done, 1);
        s_last = (v == NBLK - 1) ? 1 : 0;
    }
    __syncthreads();
    if (!s_last) return;
    __threadfence();   // acquire all blocks' g_pos / g_nbr / g_cnt writes

    // ================= sweep phase: component decomposition =================
    float2*         s_pos  = (float2*)smem;                     // 32K
    unsigned short* s_nbr2 = (unsigned short*)(smem + 32768);   // 96K
    unsigned short* s_lbl  = (unsigned short*)(smem + 131072);  // 8K
    unsigned char*  s_ca   = (unsigned char*)(smem + 139264);   // 4K
    unsigned int*   s_sc2  = (unsigned int*)(smem + 143360);    // 16K (root histogram->incl scan)
    unsigned short* s_comp = (unsigned short*)(smem + 159744);  // 8K (root-sorted ids)
    float2*         s_mv   = (float2*)(smem + 167936);          // 32K (moves scratch)
    unsigned int*   s_cur  = (unsigned int*)(smem + 167936);    // alias: scatter cursors

    #pragma unroll
    for (int s = 0; s < PPT; s++) {
        int k = tid + s * NTHR;
        s_pos[k] = g_pos[k];
        s_ca[k]  = g_cnt[k];
        s_lbl[k] = (unsigned short)k;
        s_sc2[k] = 0u;
    }
    {
        const uint4* src = (const uint4*)g_nbr;   // 96KB = 6144 uint4
        uint4* dst = (uint4*)s_nbr2;
        #pragma unroll
        for (int s = 0; s < 6; s++) dst[tid + s * NTHR] = src[tid + s * NTHR];
    }
    if (tid == 0) s_nbig = 0;
    __syncthreads();

    // ---- min-label propagation with pointer jumping (6 sync rounds) ----
    for (int r = 0; r < 6; r++) {
        unsigned nl[PPT];
        #pragma unroll
        for (int s = 0; s < PPT; s++) {
            int p = tid + s * NTHR;
            unsigned m = s_lbl[p];
            unsigned pj = s_lbl[m];            // pointer jump
            if (pj < m) m = pj;
            int c = s_ca[p];
            for (int k = 0; k < c; k++) {
                unsigned l = s_lbl[s_nbr2[k * NP + p]];
                if (l < m) m = l;
            }
            nl[s] = m;
        }
        __syncthreads();
        #pragma unroll
        for (int s = 0; s < PPT; s++) s_lbl[tid + s * NTHR] = (unsigned short)nl[s];
        __syncthreads();
    }

    // ---- histogram by root ----
    #pragma unroll
    for (int s = 0; s < PPT; s++)
        atomicAdd(&s_sc2[s_lbl[tid + s * NTHR]], 1u);
    __syncthreads();

    // ---- inclusive scan over 4096 roots (4/thread + warp shfl) ----
    {
        unsigned v[4]; unsigned run = 0u;
        int base = tid * 4;
        #pragma unroll
        for (int q = 0; q < 4; q++) { run += s_sc2[base + q]; v[q] = run; }
        unsigned tot = run;
        #pragma unroll
        for (int o = 1; o < 32; o <<= 1) {
            unsigned n = __shfl_up_sync(0xffffffffu, tot, o);
            if (lane >= o) tot += n;
        }
        if (lane == 31) ((unsigned*)s_ws)[wrp] = tot;
        unsigned lanepre = tot - run;
        __syncthreads();
        unsigned wpre = 0u;
        #pragma unroll
        for (int w = 0; w < 32; w++) { unsigned t = ((unsigned*)s_ws)[w]; if (w < wrp) wpre += t; }
        unsigned off = wpre + lanepre;
        #pragma unroll
        for (int q = 0; q < 4; q++) {
            unsigned cntq = v[q] - (q > 0 ? v[q - 1] : 0u);
            unsigned incl = v[q] + off;
            s_sc2[base + q] = incl;            // inclusive scan (persistent)
            s_cur[base + q] = incl - cntq;     // exclusive cursor (aliases s_mv)
        }
    }
    __syncthreads();
    #pragma unroll
    for (int s = 0; s < PPT; s++) {
        int p = tid + s * NTHR;
        unsigned pos = atomicAdd(&s_cur[s_lbl[p]], 1u);
        s_comp[pos] = (unsigned short)p;
    }
    __syncthreads();

    const float THR   = (float)(2.0 * 3.15e-6);     // 2*Rc
    const float THR2G = THR * THR * 1.0005f;
    const float MOVC  = (float)(2.1 * 3.15e-6);

    // ---- small components (m <= 4): per-thread local do-while, no barriers ----
    #pragma unroll
    for (int s = 0; s < PPT; s++) {
        int p = tid + s * NTHR;
        if ((int)s_lbl[p] == p) {                       // root
            int st = (p == 0) ? 0 : (int)s_sc2[p - 1];
            int m  = (int)s_sc2[p] - st;
            if (m <= 4) {
                for (int it = 0; it < 30; it++) {
                    int anyc = 0;
                    for (int u = 0; u < m; u++) {
                        int a = s_comp[st + u];
                        float2 pa = s_pos[a];
                        float mx = 0.f, my = 0.f;
                        int c = s_ca[a];
                        for (int k = 0; k < c; k++) {
                            int j = s_nbr2[k * NP + a];
                            float2 q = s_pos[j];
                            float dx = q.x - pa.x, dy = q.y - pa.y;
                            float r2 = fmaf(dx, dx, dy * dy);
                            if (r2 <= THR2G) {
                                float rinv = __frsqrt_rn(r2);
                                float absd = r2 * rinv;
                                if (absd <= THR) {
                                    float f = (MOVC - absd) * 0.5f * rinv;
                                    mx += dx * f;
                                    my += dy * f;
                                    anyc = 1;
                                }
                            }
                        }
                        s_mv[a] = make_float2(mx, my);
                    }
                    for (int u = 0; u < m; u++) {       // Jacobi apply
                        int a = s_comp[st + u];
                        float2 mv = s_mv[a];
                        float2 pc = s_pos[a];
                        s_pos[a] = make_float2(pc.x - mv.x, pc.y - mv.y);
                    }
                    if (!anyc) break;
                }
            } else {
                int idx = atomicAdd(&s_nbig, 1);
                if (idx < 256) s_bigl[idx] = (unsigned short)p;
            }
        }
    }
    __syncthreads();

    // ---- big components (m >= 5): one warp each, syncwarp-only iteration ----
    {
        int nb = s_nbig; if (nb > 256) nb = 256;
        for (int e = wrp; e < nb; e += 32) {
            int rr = s_bigl[e];
            int st = (rr == 0) ? 0 : (int)s_sc2[rr - 1];
            int m  = (int)s_sc2[rr] - st;
            if (m > 64) m = 64;
            int a0 = (lane < m) ? (int)s_comp[st + lane] : -1;
            int a1 = (lane + 32 < m) ? (int)s_comp[st + lane + 32] : -1;
            int c0 = (a0 >= 0) ? (int)s_ca[a0] : 0;
            int c1 = (a1 >= 0) ? (int)s_ca[a1] : 0;
            for (int it = 0; it < 30; it++) {
                float m0x = 0.f, m0y = 0.f, m1x = 0.f, m1y = 0.f;
                int myc = 0;
                if (a0 >= 0) {
                    float2 pa = s_pos[a0];
                    for (int k = 0; k < c0; k++) {
                        int j = s_nbr2[k * NP + a0];
                        float2 q = s_pos[j];
                        float dx = q.x - pa.x, dy = q.y - pa.y;
                        float r2 = fmaf(dx, dx, dy * dy);
                        if (r2 <= THR2G) {
                            float rinv = __frsqrt_rn(r2);
                            float absd = r2 * rinv;
                            if (absd <= THR) {
                                float f = (MOVC - absd) * 0.5f * rinv;
                                m0x += dx * f; m0y += dy * f; myc = 1;
                            }
                        }
                    }
                }
                if (a1 >= 0) {
                    float2 pa = s_pos[a1];
                    for (int k = 0; k < c1; k++) {
                        int j = s_nbr2[k * NP + a1];
                        float2 q = s_pos[j];
                        float dx = q.x - pa.x, dy = q.y - pa.y;
                        float r2 = fmaf(dx, dx, dy * dy);
                        if (r2 <= THR2G) {
                            float rinv = __frsqrt_rn(r2);
                            float absd = r2 * rinv;
                            if (absd <= THR) {
                                float f = (MOVC - absd) * 0.5f * rinv;
                                m1x += dx * f; m1y += dy * f; myc = 1;
                            }
                        }
                    }
                }
                unsigned ball = __ballot_sync(0xffffffffu, myc);
                __syncwarp();                         // reads done before writes
                if (a0 >= 0) { float2 pc = s_pos[a0]; s_pos[a0] = make_float2(pc.x - m0x, pc.y - m0y); }
                if (a1 >= 0) { float2 pc = s_pos[a1]; s_pos[a1] = make_float2(pc.x - m1x, pc.y - m1y); }
                __syncwarp();                         // writes visible before next reads
                if (!ball) break;
            }
        }
    }
    __syncthreads();

    // ---- write final positions ----
    #pragma unroll
    for (int s = 0; s < PPT; s++) {
        int p = tid + s * NTHR;
        out[p * 2 + 0] = s_pos[p].x;
        out[p * 2 + 1] = s_pos[p].y;
    }
    if (tid == 0) g_done = 0;                 // reset for next graph replay
}

// ---------------------------------------------------------------------------
extern "C" void kernel_launch(void* const* d_in, const int* in_sizes, int n_in,
                              void* d_out, int out_size) {
    const float* pre    = (const float*)d_in[0];
    const float* pim    = (const float*)d_in[1];
    const float* ore    = (const float*)d_in[2];
    const float* oim    = (const float*)d_in[3];
    const float* deltas = (const float*)d_in[4];
    const float* rnoise = (const float*)d_in[5];
    const float* tnre   = (const float*)d_in[6];
    const float* tnim   = (const float*)d_in[7];
    float* out = (float*)d_out;

    cudaFuncSetAttribute(fused_kernel, cudaFuncAttributeMaxDynamicSharedMemorySize, SMEM_BYTES);
    fused_kernel<<<NBLK, NTHR, SMEM_BYTES>>>(pre, pim, ore, oim, deltas, rnoise,
                                             tnre, tnim, out);
}